// round 1
// baseline (speedup 1.0000x reference)
#include <cuda_runtime.h>

#define BATCH 16384
#define EMBED 300
#define NCTX  10
#define NNEG  20
#define NF4   75           // 300 floats = 75 float4 per row
#define WARPS_PER_BLOCK 8
#define BLOCK_THREADS   (WARPS_PER_BLOCK * 32)
#define GRID_BLOCKS     (BATCH / WARPS_PER_BLOCK)   // 2048

// scratch for deterministic two-stage reduction (no device mallocs allowed)
__device__ float g_block_partials[GRID_BLOCKS];

__device__ __forceinline__ float log_sigmoid(float x) {
    // stable: min(x,0) - log1p(exp(-|x|))
    return fminf(x, 0.0f) - log1pf(__expf(-fabsf(x)));
}

__device__ __forceinline__ float dot4(float4 a, float4 b) {
    return a.x * b.x + a.y * b.y + a.z * b.z + a.w * b.w;
}

__global__ __launch_bounds__(BLOCK_THREADS)
void cbow_main_kernel(const int*   __restrict__ context,    // [B, NCTX]
                      const int*   __restrict__ center,     // [B]
                      const int*   __restrict__ negatives,  // [B, NNEG]
                      const float* __restrict__ ctx_w,      // [V, 300]
                      const float* __restrict__ cen_w)      // [V, 300]
{
    const int warp = threadIdx.x >> 5;
    const int lane = threadIdx.x & 31;
    const int b    = blockIdx.x * WARPS_PER_BLOCK + warp;

    // ---- gather all 31 indices for this batch element, one per lane ----
    int idx = 0;
    if (lane < NCTX)            idx = context[b * NCTX + lane];
    else if (lane == NCTX)      idx = center[b];
    else if (lane < NCTX + 1 + NNEG) idx = negatives[b * NNEG + (lane - NCTX - 1)];

    // ---- context mean: lane covers float4 slots {lane, lane+32, lane+64} ----
    float4 cm0 = make_float4(0.f, 0.f, 0.f, 0.f);
    float4 cm1 = cm0;
    float4 cm2 = cm0;
    const bool tail = (lane < NF4 - 64);   // lane < 11

    #pragma unroll
    for (int c = 0; c < NCTX; ++c) {
        int row = __shfl_sync(0xffffffffu, idx, c);
        const float4* r = reinterpret_cast<const float4*>(ctx_w + (size_t)row * EMBED);
        float4 a0 = __ldg(r + lane);
        float4 a1 = __ldg(r + lane + 32);
        cm0.x += a0.x; cm0.y += a0.y; cm0.z += a0.z; cm0.w += a0.w;
        cm1.x += a1.x; cm1.y += a1.y; cm1.z += a1.z; cm1.w += a1.w;
        if (tail) {
            float4 a2 = __ldg(r + lane + 64);
            cm2.x += a2.x; cm2.y += a2.y; cm2.z += a2.z; cm2.w += a2.w;
        }
    }
    const float inv_c = 1.0f / (float)NCTX;
    cm0.x *= inv_c; cm0.y *= inv_c; cm0.z *= inv_c; cm0.w *= inv_c;
    cm1.x *= inv_c; cm1.y *= inv_c; cm1.z *= inv_c; cm1.w *= inv_c;
    cm2.x *= inv_c; cm2.y *= inv_c; cm2.z *= inv_c; cm2.w *= inv_c;

    // ---- 21 scores: center (t=0) + 20 negatives ----
    float loss = 0.0f;
    #pragma unroll
    for (int t = 0; t < 1 + NNEG; ++t) {
        int row = __shfl_sync(0xffffffffu, idx, NCTX + t);
        const float4* r = reinterpret_cast<const float4*>(cen_w + (size_t)row * EMBED);
        float4 a0 = __ldg(r + lane);
        float4 a1 = __ldg(r + lane + 32);
        float s = dot4(a0, cm0) + dot4(a1, cm1);
        if (tail) {
            float4 a2 = __ldg(r + lane + 64);
            s += dot4(a2, cm2);
        }
        #pragma unroll
        for (int off = 16; off > 0; off >>= 1)
            s += __shfl_xor_sync(0xffffffffu, s, off);
        loss += log_sigmoid(t == 0 ? s : -s);
    }

    // ---- deterministic block reduction of -(pos_loss + neg_loss) ----
    __shared__ float sdata[WARPS_PER_BLOCK];
    if (lane == 0) sdata[warp] = -loss;
    __syncthreads();
    if (threadIdx.x == 0) {
        float tot = 0.f;
        #pragma unroll
        for (int i = 0; i < WARPS_PER_BLOCK; ++i) tot += sdata[i];
        g_block_partials[blockIdx.x] = tot;
    }
}

__global__ __launch_bounds__(256)
void cbow_reduce_kernel(float* __restrict__ out)
{
    __shared__ float sh[256];
    float s = 0.f;
    for (int i = threadIdx.x; i < GRID_BLOCKS; i += 256)
        s += g_block_partials[i];
    sh[threadIdx.x] = s;
    __syncthreads();
    #pragma unroll
    for (int off = 128; off > 0; off >>= 1) {
        if (threadIdx.x < off) sh[threadIdx.x] += sh[threadIdx.x + off];
        __syncthreads();
    }
    if (threadIdx.x == 0)
        out[0] = sh[0] / (float)BATCH;
}

extern "C" void kernel_launch(void* const* d_in, const int* in_sizes, int n_in,
                              void* d_out, int out_size)
{
    const int*   context   = (const int*)  d_in[0];
    const int*   center    = (const int*)  d_in[1];
    const int*   negatives = (const int*)  d_in[2];
    const float* ctx_w     = (const float*)d_in[3];
    const float* cen_w     = (const float*)d_in[4];
    float*       out       = (float*)d_out;

    cbow_main_kernel<<<GRID_BLOCKS, BLOCK_THREADS>>>(context, center, negatives, ctx_w, cen_w);
    cbow_reduce_kernel<<<1, 256>>>(out);
}

// round 2
// speedup vs baseline: 1.1383x; 1.1383x over previous
#include <cuda_runtime.h>

#define BATCH 16384
#define EMBED 300
#define NCTX  10
#define NNEG  20
#define NF4   75           // 300 floats = 75 float4 per row
#define WARPS_PER_BLOCK 8
#define BLOCK_THREADS   (WARPS_PER_BLOCK * 32)
#define GRID_BLOCKS     (BATCH / WARPS_PER_BLOCK)   // 2048

// Fused-reduction state (zero-initialized .bss; reset by the last block each
// call so CUDA-graph replays see a clean state).
__device__ float        g_sum;
__device__ unsigned int g_arrived;

__device__ __forceinline__ float log_sigmoid(float x) {
    // stable: min(x,0) - log1p(exp(-|x|))
    return fminf(x, 0.0f) - log1pf(__expf(-fabsf(x)));
}

__device__ __forceinline__ float dot4(float4 a, float4 b) {
    return a.x * b.x + a.y * b.y + a.z * b.z + a.w * b.w;
}

__global__ __launch_bounds__(BLOCK_THREADS)
void cbow_main_kernel(const int*   __restrict__ context,    // [B, NCTX]
                      const int*   __restrict__ center,     // [B]
                      const int*   __restrict__ negatives,  // [B, NNEG]
                      const float* __restrict__ ctx_w,      // [V, 300]
                      const float* __restrict__ cen_w,      // [V, 300]
                      float*       __restrict__ out)
{
    const int warp = threadIdx.x >> 5;
    const int lane = threadIdx.x & 31;
    const int b    = blockIdx.x * WARPS_PER_BLOCK + warp;

    // ---- gather all 31 indices for this batch element, one per lane ----
    int idx = 0;
    if (lane < NCTX)                 idx = context[b * NCTX + lane];
    else if (lane == NCTX)           idx = center[b];
    else if (lane < NCTX + 1 + NNEG) idx = negatives[b * NNEG + (lane - NCTX - 1)];

    // ---- context mean: lane covers float4 slots {lane, lane+32, lane+64} ----
    float4 cm0 = make_float4(0.f, 0.f, 0.f, 0.f);
    float4 cm1 = cm0;
    float4 cm2 = cm0;
    const bool tail = (lane < NF4 - 64);   // lane < 11

    #pragma unroll
    for (int c = 0; c < NCTX; ++c) {
        int row = __shfl_sync(0xffffffffu, idx, c);
        const float4* r = reinterpret_cast<const float4*>(ctx_w + (size_t)row * EMBED);
        float4 a0 = __ldg(r + lane);
        float4 a1 = __ldg(r + lane + 32);
        cm0.x += a0.x; cm0.y += a0.y; cm0.z += a0.z; cm0.w += a0.w;
        cm1.x += a1.x; cm1.y += a1.y; cm1.z += a1.z; cm1.w += a1.w;
        if (tail) {
            float4 a2 = __ldg(r + lane + 64);
            cm2.x += a2.x; cm2.y += a2.y; cm2.z += a2.z; cm2.w += a2.w;
        }
    }
    const float inv_c = 1.0f / (float)NCTX;
    cm0.x *= inv_c; cm0.y *= inv_c; cm0.z *= inv_c; cm0.w *= inv_c;
    cm1.x *= inv_c; cm1.y *= inv_c; cm1.z *= inv_c; cm1.w *= inv_c;
    cm2.x *= inv_c; cm2.y *= inv_c; cm2.z *= inv_c; cm2.w *= inv_c;

    // ---- 21 scores: center (t=0) + 20 negatives ----
    float loss = 0.0f;
    #pragma unroll
    for (int t = 0; t < 1 + NNEG; ++t) {
        int row = __shfl_sync(0xffffffffu, idx, NCTX + t);
        const float4* r = reinterpret_cast<const float4*>(cen_w + (size_t)row * EMBED);
        float4 a0 = __ldg(r + lane);
        float4 a1 = __ldg(r + lane + 32);
        float s = dot4(a0, cm0) + dot4(a1, cm1);
        if (tail) {
            float4 a2 = __ldg(r + lane + 64);
            s += dot4(a2, cm2);
        }
        #pragma unroll
        for (int off = 16; off > 0; off >>= 1)
            s += __shfl_xor_sync(0xffffffffu, s, off);
        loss += log_sigmoid(t == 0 ? s : -s);
    }

    // ---- block partial of -(pos_loss + neg_loss) ----
    __shared__ float sdata[WARPS_PER_BLOCK];
    if (lane == 0) sdata[warp] = -loss;
    __syncthreads();

    // ---- fused grid reduction: last block to arrive finalizes ----
    if (threadIdx.x == 0) {
        float tot = 0.f;
        #pragma unroll
        for (int i = 0; i < WARPS_PER_BLOCK; ++i) tot += sdata[i];

        atomicAdd(&g_sum, tot);
        __threadfence();
        unsigned prev = atomicAdd(&g_arrived, 1u);
        if (prev == GRID_BLOCKS - 1) {
            // all block partials are in g_sum (their adds precede their
            // counter increments, fenced)
            float total = g_sum;
            out[0] = total / (float)BATCH;
            // reset for the next graph replay
            g_sum = 0.0f;
            __threadfence();
            g_arrived = 0u;
        }
    }
}

extern "C" void kernel_launch(void* const* d_in, const int* in_sizes, int n_in,
                              void* d_out, int out_size)
{
    const int*   context   = (const int*)  d_in[0];
    const int*   center    = (const int*)  d_in[1];
    const int*   negatives = (const int*)  d_in[2];
    const float* ctx_w     = (const float*)d_in[3];
    const float* cen_w     = (const float*)d_in[4];
    float*       out       = (float*)d_out;

    cbow_main_kernel<<<GRID_BLOCKS, BLOCK_THREADS>>>(
        context, center, negatives, ctx_w, cen_w, out);
}